// round 7
// baseline (speedup 1.0000x reference)
#include <cuda_runtime.h>

// Problem constants
#define BB 2
#define CC 128
#define GG 8
#define CG 16
#define HH 64
#define WW 64
#define PH 78              // HH + 14 (pad 7 each side)
#define PW 78

// Transposed scratch: channel-fastest (16 ch per group contiguous = 64B)
__device__ float g_q [BB*GG*HH*WW*CG];          // [b][g][h][w][c]
__device__ float g_kp[BB*GG*PH*PW*CG];          // [b][g][h+7][w+7][c], zero halo
__device__ float g_vp[BB*GG*PH*PW*CG];

// ---------------------------------------------------------------------------
// Kernel 0: zero the padded K/V buffers (halo must read as 0)
// ---------------------------------------------------------------------------
__global__ __launch_bounds__(256) void zero_pad()
{
    const int N4 = BB*GG*PH*PW*CG / 4;
    int i = blockIdx.x * 256 + threadIdx.x;
    if (i < N4) {
        ((float4*)g_kp)[i] = make_float4(0.f, 0.f, 0.f, 0.f);
        ((float4*)g_vp)[i] = make_float4(0.f, 0.f, 0.f, 0.f);
    }
}

// ---------------------------------------------------------------------------
// Kernel 1: Q/K/V 1x1 conv as tiled GEMM, writing transposed (+padded) layout.
// grid.z: 0=Q(from fm[:,128:]), 1=K, 2=V. 256 thr, 64 pixels x 128 oc.
// ---------------------------------------------------------------------------
__global__ __launch_bounds__(256) void qkv_gemm(
    const float* __restrict__ fm,
    const float* __restrict__ wq,
    const float* __restrict__ wk,
    const float* __restrict__ wv)
{
    __shared__ float wS[128][33];
    __shared__ float xS[32][64];

    int z = blockIdx.z;
    const float* w = (z == 0) ? wq : (z == 1 ? wk : wv);
    int coff       = (z == 0) ? 128 : 0;

    int t    = threadIdx.x;
    int pix0 = blockIdx.x * 64;
    int b    = pix0 >> 12;
    int rem0 = pix0 & 4095;

    const float* xbase = fm + ((size_t)(b * 256 + coff) << 12) + rem0;

    int ocb = (t >> 4) << 3;   // 0..120 step 8 (stays inside one group of 16)
    int pxb = (t & 15) << 2;   // 0..60 step 4

    float acc[8][4];
#pragma unroll
    for (int u = 0; u < 8; u++)
#pragma unroll
        for (int p = 0; p < 4; p++) acc[u][p] = 0.f;

    for (int ic0 = 0; ic0 < 128; ic0 += 32) {
#pragma unroll
        for (int j = 0; j < 16; j++) {
            int idx = t + j * 256;
            wS[idx >> 5][idx & 31] = w[(idx >> 5) * 128 + ic0 + (idx & 31)];
        }
#pragma unroll
        for (int j = 0; j < 8; j++) {
            int idx = t + j * 256;
            xS[idx >> 6][idx & 63] =
                xbase[(size_t)(ic0 + (idx >> 6)) * 4096 + (idx & 63)];
        }
        __syncthreads();

#pragma unroll
        for (int kk = 0; kk < 32; kk++) {
            float x0 = xS[kk][pxb + 0];
            float x1 = xS[kk][pxb + 1];
            float x2 = xS[kk][pxb + 2];
            float x3 = xS[kk][pxb + 3];
#pragma unroll
            for (int u = 0; u < 8; u++) {
                float wv_ = wS[ocb + u][kk];
                acc[u][0] += wv_ * x0;
                acc[u][1] += wv_ * x1;
                acc[u][2] += wv_ * x2;
                acc[u][3] += wv_ * x3;
            }
        }
        __syncthreads();
    }

    // Epilogue: transposed writes, float4 along channel
    int g  = ocb >> 4;
    int c0 = ocb & 15;         // 0 or 8
#pragma unroll
    for (int p = 0; p < 4; p++) {
        int pix = rem0 + pxb + p;
        int h = pix >> 6;
        int ww_ = pix & 63;
        float4 v0 = make_float4(acc[0][p], acc[1][p], acc[2][p], acc[3][p]);
        float4 v1 = make_float4(acc[4][p], acc[5][p], acc[6][p], acc[7][p]);
        if (z == 0) {
            size_t base = ((size_t)((b * GG + g) * HH + h) * WW + ww_) * CG + c0;
            *(float4*)(g_q + base)     = v0;
            *(float4*)(g_q + base + 4) = v1;
        } else {
            size_t base = ((size_t)((b * GG + g) * PH + (h + 7)) * PW + (ww_ + 7)) * CG + c0;
            float* dst = (z == 1) ? g_kp : g_vp;
            *(float4*)(dst + base)     = v0;
            *(float4*)(dst + base + 4) = v1;
        }
    }
}

// ---------------------------------------------------------------------------
// Kernel 2: fused windowed attention. Warp = 8 pixels x 4 channel-quartets.
// lane = c4*8 + px. Block 256 thr = 8 warps = 8x8 pixel tile.
// All K/V via LDG.128 from padded L2-resident maps; logits reduced by shfl.
// ---------------------------------------------------------------------------
__global__ __launch_bounds__(256) void attn_kernel(
    const float* __restrict__ relh,
    const float* __restrict__ relw,
    float* __restrict__ out)
{
    int tid  = threadIdx.x;
    int wid  = tid >> 5;
    int lane = tid & 31;
    int px   = lane & 7;
    int c4   = lane >> 3;          // channel quartet 0..3
    int cof  = c4 << 2;

    int bz = blockIdx.z;
    int b  = bz >> 3;
    int g  = bz & 7;
    int h  = blockIdx.y * 8 + wid;
    int w  = blockIdx.x * 8 + px;

    const float* Kb = g_kp + (size_t)(b * GG + g) * (PH * PW * CG);
    const float* Vb = g_vp + (size_t)(b * GG + g) * (PH * PW * CG);

    float4 q = *(const float4*)(g_q +
        ((size_t)((b * GG + g) * HH + h) * WW + w) * CG + cof);

    // Partial separable rel bias over this lane's 4 channels
    float bias[7];
#pragma unroll
    for (int i = 0; i < 7; i++) bias[i] = 0.f;
    {
        const float* rel = (g < 4) ? (relh + (g * CG + cof) * 7)
                                   : (relw + ((g - 4) * CG + cof) * 7);
        float qs[4] = {q.x, q.y, q.z, q.w};
#pragma unroll
        for (int cc = 0; cc < 4; cc++)
#pragma unroll
            for (int i = 0; i < 7; i++)
                bias[i] += qs[cc] * rel[cc * 7 + i];
    }

    int ph = h + 7, pw = w + 7;

    // ---- Main 7x7 window (offsets -3..+3) ----
    float lg[49];
#pragma unroll
    for (int di = 0; di < 7; di++)
#pragma unroll
        for (int dj = 0; dj < 7; dj++) {
            const float4 kv = *(const float4*)(Kb +
                ((size_t)(ph - 3 + di) * PW + (pw - 3 + dj)) * CG + cof);
            float bb = (g < 4) ? bias[di] : bias[dj];
            lg[di * 7 + dj] =
                fmaf(q.x, kv.x, fmaf(q.y, kv.y, fmaf(q.z, kv.z, fmaf(q.w, kv.w, bb))));
        }
#pragma unroll
    for (int p = 0; p < 49; p++) {
        lg[p] += __shfl_xor_sync(0xffffffffu, lg[p], 8);
        lg[p] += __shfl_xor_sync(0xffffffffu, lg[p], 16);
    }
    float m = lg[0];
#pragma unroll
    for (int p = 1; p < 49; p++) m = fmaxf(m, lg[p]);
    float s = 0.f;
#pragma unroll
    for (int p = 0; p < 49; p++) { lg[p] = __expf(lg[p] - m); s += lg[p]; }
    float inv = 1.f / s;

    float o0 = 0.f, o1 = 0.f, o2 = 0.f, o3 = 0.f;
#pragma unroll
    for (int di = 0; di < 7; di++)
#pragma unroll
        for (int dj = 0; dj < 7; dj++) {
            const float4 vv = *(const float4*)(Vb +
                ((size_t)(ph - 3 + di) * PW + (pw - 3 + dj)) * CG + cof);
            float a = lg[di * 7 + dj] * inv;
            o0 += a * vv.x; o1 += a * vv.y; o2 += a * vv.z; o3 += a * vv.w;
        }

    // ---- Refine: row window (same h, w-7..w+7), no bias ----
    {
        float lr[15];
#pragma unroll
        for (int j = 0; j < 15; j++) {
            const float4 kv = *(const float4*)(Kb +
                ((size_t)ph * PW + (pw - 7 + j)) * CG + cof);
            lr[j] = fmaf(q.x, kv.x, fmaf(q.y, kv.y, fmaf(q.z, kv.z, q.w * kv.w)));
        }
#pragma unroll
        for (int j = 0; j < 15; j++) {
            lr[j] += __shfl_xor_sync(0xffffffffu, lr[j], 8);
            lr[j] += __shfl_xor_sync(0xffffffffu, lr[j], 16);
        }
        float mr = lr[0];
#pragma unroll
        for (int j = 1; j < 15; j++) mr = fmaxf(mr, lr[j]);
        float sr = 0.f;
#pragma unroll
        for (int j = 0; j < 15; j++) { lr[j] = __expf(lr[j] - mr); sr += lr[j]; }
        float ir = 1.f / sr;
#pragma unroll
        for (int j = 0; j < 15; j++) {
            const float4 vv = *(const float4*)(Vb +
                ((size_t)ph * PW + (pw - 7 + j)) * CG + cof);
            float a = lr[j] * ir;
            o0 += a * vv.x; o1 += a * vv.y; o2 += a * vv.z; o3 += a * vv.w;
        }
    }

    // ---- Refine: column window (same w, h-7..h+7), no bias ----
    {
        float lc[15];
#pragma unroll
        for (int j = 0; j < 15; j++) {
            const float4 kv = *(const float4*)(Kb +
                ((size_t)(ph - 7 + j) * PW + pw) * CG + cof);
            lc[j] = fmaf(q.x, kv.x, fmaf(q.y, kv.y, fmaf(q.z, kv.z, q.w * kv.w)));
        }
#pragma unroll
        for (int j = 0; j < 15; j++) {
            lc[j] += __shfl_xor_sync(0xffffffffu, lc[j], 8);
            lc[j] += __shfl_xor_sync(0xffffffffu, lc[j], 16);
        }
        float mc = lc[0];
#pragma unroll
        for (int j = 1; j < 15; j++) mc = fmaxf(mc, lc[j]);
        float sc = 0.f;
#pragma unroll
        for (int j = 0; j < 15; j++) { lc[j] = __expf(lc[j] - mc); sc += lc[j]; }
        float ic = 1.f / sc;
#pragma unroll
        for (int j = 0; j < 15; j++) {
            const float4 vv = *(const float4*)(Vb +
                ((size_t)(ph - 7 + j) * PW + pw) * CG + cof);
            float a = lc[j] * ic;
            o0 += a * vv.x; o1 += a * vv.y; o2 += a * vv.z; o3 += a * vv.w;
        }
    }

    // Output: standard [b][oc][h][w] layout
    size_t ob = ((size_t)(b * CC + g * CG + cof) << 12) + h * WW + w;
    out[ob]          = o0;
    out[ob + 4096]   = o1;
    out[ob + 2*4096] = o2;
    out[ob + 3*4096] = o3;
}

// ---------------------------------------------------------------------------
extern "C" void kernel_launch(void* const* d_in, const int* in_sizes, int n_in,
                              void* d_out, int out_size)
{
    const float* fm = (const float*)d_in[0];
    const float* wq = (const float*)d_in[1];
    const float* wk = (const float*)d_in[2];
    const float* wv = (const float*)d_in[3];
    const float* rh = (const float*)d_in[4];
    const float* rw = (const float*)d_in[5];
    float* out = (float*)d_out;

    const int N4 = BB*GG*PH*PW*CG / 4;
    zero_pad<<<(N4 + 255) / 256, 256>>>();

    dim3 g1(128, 1, 3);
    qkv_gemm<<<g1, 256>>>(fm, wq, wk, wv);

    dim3 g2(WW / 8, HH / 8, BB * GG);      // (8, 8, 16)
    attn_kernel<<<g2, 256>>>(rh, rw, out);
}

// round 9
// speedup vs baseline: 1.5246x; 1.5246x over previous
#include <cuda_runtime.h>

// Problem constants
#define BB 2
#define CC 128
#define GG 8
#define CG 16
#define HH 64
#define WW 64

// Attention tile: 8 rows x 16 cols, halo 7 each side
#define TH 8
#define TW 16
#define SH 22              // TH + 14
#define SW 30              // TW + 14
#define NPOS (SH*SW)       // 660 halo positions
#define SMEM_BYTES (2*NPOS*CG*4)   // K + V, 84480 B

// Transposed scratch: [b][g][h][w][c], 16-ch contiguous (64B)
__device__ float g_q[BB*GG*HH*WW*CG];
__device__ float g_k[BB*GG*HH*WW*CG];
__device__ float g_v[BB*GG*HH*WW*CG];

typedef unsigned long long ull;
__device__ __forceinline__ ull pk2(float lo, float hi) {
    ull r; asm("mov.b64 %0, {%1, %2};" : "=l"(r) : "f"(lo), "f"(hi)); return r;
}
__device__ __forceinline__ void upk2(ull v, float& lo, float& hi) {
    asm("mov.b64 {%0, %1}, %2;" : "=f"(lo), "=f"(hi) : "l"(v));
}
__device__ __forceinline__ void fma2(ull& d, ull a, ull b) {
    asm("fma.rn.f32x2 %0, %1, %2, %0;" : "+l"(d) : "l"(a), "l"(b));
}

// ---------------------------------------------------------------------------
// Kernel 1: Q/K/V 1x1 conv as tiled GEMM (packed f32x2 FMA), transposed write.
// grid.z: 0=Q(from fm[:,128:]), 1=K, 2=V. 256 thr, 64 pixels x 128 oc.
// ---------------------------------------------------------------------------
__global__ __launch_bounds__(256) void qkv_gemm(
    const float* __restrict__ fm,
    const float* __restrict__ wq,
    const float* __restrict__ wk,
    const float* __restrict__ wv)
{
    __shared__ float wS[128][33];
    __shared__ float xS[32][64];

    int z = blockIdx.z;
    const float* w = (z == 0) ? wq : (z == 1 ? wk : wv);
    int coff       = (z == 0) ? 128 : 0;

    int t    = threadIdx.x;
    int pix0 = blockIdx.x * 64;
    int b    = pix0 >> 12;
    int rem0 = pix0 & 4095;

    const float* xbase = fm + ((size_t)(b * 256 + coff) << 12) + rem0;

    int ocb = (t >> 4) << 3;   // 0..120 step 8 (inside one 16-ch group)
    int pxb = (t & 15) << 2;   // 0..60 step 4

    ull acc2[8][2];
#pragma unroll
    for (int u = 0; u < 8; u++) { acc2[u][0] = pk2(0.f, 0.f); acc2[u][1] = acc2[u][0]; }

    for (int ic0 = 0; ic0 < 128; ic0 += 32) {
#pragma unroll
        for (int j = 0; j < 16; j++) {
            int idx = t + j * 256;
            wS[idx >> 5][idx & 31] = w[(idx >> 5) * 128 + ic0 + (idx & 31)];
        }
#pragma unroll
        for (int j = 0; j < 8; j++) {
            int idx = t + j * 256;
            xS[idx >> 6][idx & 63] =
                xbase[(size_t)(ic0 + (idx >> 6)) * 4096 + (idx & 63)];
        }
        __syncthreads();

#pragma unroll
        for (int kk = 0; kk < 32; kk++) {
            float2 xa = *(const float2*)&xS[kk][pxb];
            float2 xb = *(const float2*)&xS[kk][pxb + 2];
            ull X01 = pk2(xa.x, xa.y);
            ull X23 = pk2(xb.x, xb.y);
#pragma unroll
            for (int u = 0; u < 8; u++) {
                float wv_ = wS[ocb + u][kk];
                ull W = pk2(wv_, wv_);
                fma2(acc2[u][0], W, X01);
                fma2(acc2[u][1], W, X23);
            }
        }
        __syncthreads();
    }

    float acc[8][4];
#pragma unroll
    for (int u = 0; u < 8; u++) {
        upk2(acc2[u][0], acc[u][0], acc[u][1]);
        upk2(acc2[u][1], acc[u][2], acc[u][3]);
    }

    float* dst = (z == 0) ? g_q : (z == 1 ? g_k : g_v);
    int g  = ocb >> 4;
    int c0 = ocb & 15;         // 0 or 8
#pragma unroll
    for (int p = 0; p < 4; p++) {
        int pix = rem0 + pxb + p;
        int h = pix >> 6;
        int ww_ = pix & 63;
        size_t base = ((size_t)((b * GG + g) * HH + h) * WW + ww_) * CG + c0;
        *(float4*)(dst + base)     = make_float4(acc[0][p], acc[1][p], acc[2][p], acc[3][p]);
        *(float4*)(dst + base + 4) = make_float4(acc[4][p], acc[5][p], acc[6][p], acc[7][p]);
    }
}

// ---------------------------------------------------------------------------
// Kernel 2: fused windowed attention. Block = 8x16 pixel tile, 512 threads.
// lane = px*4 + c4 (channel quartet fastest -> conflict-free LDS.128).
// Streaming softmax over the 7 main-window rows keeps regs ~50.
// ---------------------------------------------------------------------------
__global__ __launch_bounds__(512, 2) void attn_kernel(
    const float* __restrict__ relh,
    const float* __restrict__ relw,
    float* __restrict__ out)
{
    extern __shared__ float sh[];
    float* Ks = sh;                  // NPOS * 16
    float* Vs = sh + NPOS * CG;

    int tid  = threadIdx.x;
    int wid  = tid >> 5;
    int lane = tid & 31;
    int c4   = lane & 3;
    int pxw  = lane >> 2;            // 0..7
    int cof  = c4 << 2;

    int bz = blockIdx.z;
    int b  = bz >> 3;
    int g  = bz & 7;
    int h0 = blockIdx.y * TH;
    int w0 = blockIdx.x * TW;

    int row = wid >> 1;                       // 0..7
    int col = (wid & 1) * 8 + pxw;            // 0..15
    int h = h0 + row, w = w0 + col;

    const float* Kg = g_k + (size_t)(b * GG + g) * (HH * WW * CG);
    const float* Vg = g_v + (size_t)(b * GG + g) * (HH * WW * CG);

    // Halo load with zero fill (contiguous 16B slots; rows contiguous in gmem)
    for (int idx = tid; idx < NPOS * 4; idx += 512) {
        int pos = idx >> 2;
        int cq  = (idx & 3) << 2;
        int r   = pos / SW;
        int cl  = pos - r * SW;
        int gh  = h0 - 7 + r;
        int gw  = w0 - 7 + cl;
        float4 kv = make_float4(0.f, 0.f, 0.f, 0.f);
        float4 vv = kv;
        if ((unsigned)gh < HH && (unsigned)gw < WW) {
            size_t off = ((size_t)(gh * WW + gw)) * CG + cq;
            kv = *(const float4*)(Kg + off);
            vv = *(const float4*)(Vg + off);
        }
        *(float4*)(Ks + pos * CG + cq) = kv;
        *(float4*)(Vs + pos * CG + cq) = vv;
    }
    __syncthreads();

    float4 q = *(const float4*)(g_q +
        ((size_t)((b * GG + g) * HH + h) * WW + w) * CG + cof);
    float qs[4] = {q.x, q.y, q.z, q.w};

    // Partial (this quartet's) separable rel bias; completed by the shfl-sum
    float bias[7];
#pragma unroll
    for (int i = 0; i < 7; i++) bias[i] = 0.f;
    {
        const float* rel = (g < 4) ? (relh + (g * CG + cof) * 7)
                                   : (relw + ((g - 4) * CG + cof) * 7);
#pragma unroll
        for (int cc = 0; cc < 4; cc++)
#pragma unroll
            for (int i = 0; i < 7; i++)
                bias[i] += qs[cc] * rel[cc * 7 + i];
    }

    int lr_ = row + 7, lc_ = col + 7;        // local (halo) center coords

    // ---- Main 7x7 window, streaming softmax over rows ----
    float m = -1e30f, s = 0.f;
    float o0 = 0.f, o1 = 0.f, o2 = 0.f, o3 = 0.f;
#pragma unroll
    for (int di = 0; di < 7; di++) {
        const float* kb = Ks + ((lr_ - 3 + di) * SW + (lc_ - 3)) * CG + cof;
        float lg[7];
#pragma unroll
        for (int dj = 0; dj < 7; dj++) {
            float4 kv = *(const float4*)(kb + dj * CG);
            float bb = (g < 4) ? bias[di] : bias[dj];
            lg[dj] = fmaf(q.x, kv.x, fmaf(q.y, kv.y,
                     fmaf(q.z, kv.z, fmaf(q.w, kv.w, bb))));
        }
#pragma unroll
        for (int dj = 0; dj < 7; dj++) {
            lg[dj] += __shfl_xor_sync(0xffffffffu, lg[dj], 1);
            lg[dj] += __shfl_xor_sync(0xffffffffu, lg[dj], 2);
        }
        float rm = lg[0];
#pragma unroll
        for (int dj = 1; dj < 7; dj++) rm = fmaxf(rm, lg[dj]);
        float mn = fmaxf(m, rm);
        float f  = __expf(m - mn);
        s *= f; o0 *= f; o1 *= f; o2 *= f; o3 *= f;
        const float* vb = Vs + ((lr_ - 3 + di) * SW + (lc_ - 3)) * CG + cof;
#pragma unroll
        for (int dj = 0; dj < 7; dj++) {
            float e = __expf(lg[dj] - mn);
            s += e;
            float4 vv = *(const float4*)(vb + dj * CG);
            o0 += e * vv.x; o1 += e * vv.y; o2 += e * vv.z; o3 += e * vv.w;
        }
        m = mn;
    }
    {
        float inv = 1.f / s;
        o0 *= inv; o1 *= inv; o2 *= inv; o3 *= inv;
    }

    // ---- Refine: row window (same h, w-7..w+7) ----
    {
        const float* kb = Ks + (lr_ * SW + col) * CG + cof;
        float lr[15];
#pragma unroll
        for (int j = 0; j < 15; j++) {
            float4 kv = *(const float4*)(kb + j * CG);
            lr[j] = fmaf(q.x, kv.x, fmaf(q.y, kv.y, fmaf(q.z, kv.z, q.w * kv.w)));
        }
#pragma unroll
        for (int j = 0; j < 15; j++) {
            lr[j] += __shfl_xor_sync(0xffffffffu, lr[j], 1);
            lr[j] += __shfl_xor_sync(0xffffffffu, lr[j], 2);
        }
        float mr = lr[0];
#pragma unroll
        for (int j = 1; j < 15; j++) mr = fmaxf(mr, lr[j]);
        float sr = 0.f;
#pragma unroll
        for (int j = 0; j < 15; j++) { lr[j] = __expf(lr[j] - mr); sr += lr[j]; }
        float ir = 1.f / sr;
        const float* vb = Vs + (lr_ * SW + col) * CG + cof;
#pragma unroll
        for (int j = 0; j < 15; j++) {
            float a = lr[j] * ir;
            float4 vv = *(const float4*)(vb + j * CG);
            o0 += a * vv.x; o1 += a * vv.y; o2 += a * vv.z; o3 += a * vv.w;
        }
    }

    // ---- Refine: column window (same w, h-7..h+7) ----
    {
        const float* kb = Ks + (row * SW + lc_) * CG + cof;
        float lc[15];
#pragma unroll
        for (int j = 0; j < 15; j++) {
            float4 kv = *(const float4*)(kb + j * SW * CG);
            lc[j] = fmaf(q.x, kv.x, fmaf(q.y, kv.y, fmaf(q.z, kv.z, q.w * kv.w)));
        }
#pragma unroll
        for (int j = 0; j < 15; j++) {
            lc[j] += __shfl_xor_sync(0xffffffffu, lc[j], 1);
            lc[j] += __shfl_xor_sync(0xffffffffu, lc[j], 2);
        }
        float mc = lc[0];
#pragma unroll
        for (int j = 1; j < 15; j++) mc = fmaxf(mc, lc[j]);
        float sc = 0.f;
#pragma unroll
        for (int j = 0; j < 15; j++) { lc[j] = __expf(lc[j] - mc); sc += lc[j]; }
        float ic = 1.f / sc;
        const float* vb = Vs + (row * SW + lc_) * CG + cof;
#pragma unroll
        for (int j = 0; j < 15; j++) {
            float a = lc[j] * ic;
            float4 vv = *(const float4*)(vb + j * SW * CG);
            o0 += a * vv.x; o1 += a * vv.y; o2 += a * vv.z; o3 += a * vv.w;
        }
    }

    // Output: standard [b][oc][h][w]
    size_t ob = ((size_t)(b * CC + g * CG + cof) << 12) + h * WW + w;
    out[ob]          = o0;
    out[ob + 4096]   = o1;
    out[ob + 2*4096] = o2;
    out[ob + 3*4096] = o3;
}

// ---------------------------------------------------------------------------
extern "C" void kernel_launch(void* const* d_in, const int* in_sizes, int n_in,
                              void* d_out, int out_size)
{
    const float* fm = (const float*)d_in[0];
    const float* wq = (const float*)d_in[1];
    const float* wk = (const float*)d_in[2];
    const float* wv = (const float*)d_in[3];
    const float* rh = (const float*)d_in[4];
    const float* rw = (const float*)d_in[5];
    float* out = (float*)d_out;

    cudaFuncSetAttribute(attn_kernel,
                         cudaFuncAttributeMaxDynamicSharedMemorySize, SMEM_BYTES);

    dim3 g1(128, 1, 3);
    qkv_gemm<<<g1, 256>>>(fm, wq, wk, wv);

    dim3 g2(WW / TW, HH / TH, BB * GG);    // (4, 8, 16)
    attn_kernel<<<g2, 512, SMEM_BYTES>>>(rh, rw, out);
}

// round 10
// speedup vs baseline: 1.5320x; 1.0049x over previous
#include <cuda_runtime.h>

// Problem constants
#define BB 2
#define CC 128
#define GG 8
#define CG 16
#define HH 64
#define WW 64

// Attention tile: 8 rows x 16 cols, halo 7 each side
#define TH 8
#define TW 16
#define SH 22              // TH + 14
#define SW 30              // TW + 14
#define NPOS (SH*SW)       // 660 halo positions
#define SMEM_BYTES (2*NPOS*CG*4)   // K + V, 84480 B

#define L2E 1.4426950408889634f

// Transposed scratch: [b][g][h][w][c], 16-ch contiguous (64B)
__device__ float g_q[BB*GG*HH*WW*CG];
__device__ float g_k[BB*GG*HH*WW*CG];
__device__ float g_v[BB*GG*HH*WW*CG];

typedef unsigned long long ull;
__device__ __forceinline__ ull pk2(float lo, float hi) {
    ull r; asm("mov.b64 %0, {%1, %2};" : "=l"(r) : "f"(lo), "f"(hi)); return r;
}
__device__ __forceinline__ void upk2(ull v, float& lo, float& hi) {
    asm("mov.b64 {%0, %1}, %2;" : "=f"(lo), "=f"(hi) : "l"(v));
}
__device__ __forceinline__ void fma2(ull& d, ull a, ull b) {
    asm("fma.rn.f32x2 %0, %1, %2, %0;" : "+l"(d) : "l"(a), "l"(b));
}
__device__ __forceinline__ void mul2(ull& d, ull a, ull b) {
    asm("mul.rn.f32x2 %0, %1, %2;" : "=l"(d) : "l"(a), "l"(b));
}
__device__ __forceinline__ float ex2(float x) {
    float r; asm("ex2.approx.f32 %0, %1;" : "=f"(r) : "f"(x)); return r;
}

// ---------------------------------------------------------------------------
// Kernel 1: Q/K/V 1x1 conv as tiled GEMM. Tile 64 px x 128 oc, 256 threads,
// thread = 4 px x 8 oc, packed f32x2 FMAs. grid.z: 0=Q, 1=K, 2=V.
// ---------------------------------------------------------------------------
__global__ __launch_bounds__(256) void qkv_gemm(
    const float* __restrict__ fm,
    const float* __restrict__ wq,
    const float* __restrict__ wk,
    const float* __restrict__ wv)
{
    __shared__ float wT[32][132];   // [kk][oc] transposed, padded (132*4 % 16 == 0)
    __shared__ float xS[32][64];    // [kk][px]

    int z = blockIdx.z;
    const float* w = (z == 0) ? wq : (z == 1 ? wk : wv);
    int coff       = (z == 0) ? 128 : 0;

    int t    = threadIdx.x;
    int pix0 = blockIdx.x * 64;
    int b    = pix0 >> 12;
    int rem0 = pix0 & 4095;

    const float* xbase = fm + ((size_t)(b * 256 + coff) << 12) + rem0;

    int px0 = (t & 15) << 2;   // 0..60 step 4 (contiguous float4 lanes)
    int oc0 = (t >> 4) << 3;   // 0..120 step 8

    ull acc[4][4];             // [px][oc pair]
#pragma unroll
    for (int p = 0; p < 4; p++)
#pragma unroll
        for (int u = 0; u < 4; u++) acc[p][u] = pk2(0.f, 0.f);

    for (int ic0 = 0; ic0 < 128; ic0 += 32) {
        // weights transposed: wT[ic][oc], coalesced gmem read
#pragma unroll
        for (int j = 0; j < 16; j++) {
            int idx = t + j * 256;
            int oc = idx >> 5, ic = idx & 31;
            wT[ic][oc] = w[oc * 128 + ic0 + ic];
        }
        // activations: xS[ic][px]
#pragma unroll
        for (int j = 0; j < 8; j++) {
            int idx = t + j * 256;
            int ic = idx >> 6, px = idx & 63;
            xS[ic][px] = xbase[(size_t)(ic0 + ic) * 4096 + px];
        }
        __syncthreads();

#pragma unroll
        for (int kk = 0; kk < 32; kk++) {
            ulonglong2 wa = *(const ulonglong2*)&wT[kk][oc0];       // oc0..3
            ulonglong2 wb = *(const ulonglong2*)&wT[kk][oc0 + 4];   // oc4..7
            float4 x = *(const float4*)&xS[kk][px0];
            float xs[4] = {x.x, x.y, x.z, x.w};
#pragma unroll
            for (int p = 0; p < 4; p++) {
                ull xp = pk2(xs[p], xs[p]);
                fma2(acc[p][0], xp, wa.x);
                fma2(acc[p][1], xp, wa.y);
                fma2(acc[p][2], xp, wb.x);
                fma2(acc[p][3], xp, wb.y);
            }
        }
        __syncthreads();
    }

    float* dst = (z == 0) ? g_q : (z == 1 ? g_k : g_v);
    int g  = oc0 >> 4;
    int c0 = oc0 & 15;         // 0 or 8
#pragma unroll
    for (int p = 0; p < 4; p++) {
        int pix = rem0 + px0 + p;
        int h = pix >> 6;
        int ww_ = pix & 63;
        float a0, a1, a2, a3, a4, a5, a6, a7;
        upk2(acc[p][0], a0, a1); upk2(acc[p][1], a2, a3);
        upk2(acc[p][2], a4, a5); upk2(acc[p][3], a6, a7);
        size_t base = ((size_t)((b * GG + g) * HH + h) * WW + ww_) * CG + c0;
        *(float4*)(dst + base)     = make_float4(a0, a1, a2, a3);
        *(float4*)(dst + base + 4) = make_float4(a4, a5, a6, a7);
    }
}

// ---------------------------------------------------------------------------
// Kernel 2: fused windowed attention. Block = 8x16 pixel tile, 512 threads.
// lane = px*4 + c4 (channel quartet fastest -> conflict-free contiguous LDS).
// No-max softmax (exact up to fp range; logits << 88) + ex2.approx with
// log2e folded into q. V accumulation in packed f32x2.
// ---------------------------------------------------------------------------
__global__ __launch_bounds__(512, 2) void attn_kernel(
    const float* __restrict__ relh,
    const float* __restrict__ relw,
    float* __restrict__ out)
{
    extern __shared__ float sh[];
    float* Ks = sh;                  // NPOS * 16
    float* Vs = sh + NPOS * CG;

    int tid  = threadIdx.x;
    int wid  = tid >> 5;
    int lane = tid & 31;
    int c4   = lane & 3;
    int pxw  = lane >> 2;            // 0..7
    int cof  = c4 << 2;

    int bz = blockIdx.z;
    int b  = bz >> 3;
    int g  = bz & 7;
    int h0 = blockIdx.y * TH;
    int w0 = blockIdx.x * TW;

    int row = wid >> 1;                       // 0..7
    int col = (wid & 1) * 8 + pxw;            // 0..15
    int h = h0 + row, w = w0 + col;

    const float* Kg = g_k + (size_t)(b * GG + g) * (HH * WW * CG);
    const float* Vg = g_v + (size_t)(b * GG + g) * (HH * WW * CG);

    // Halo load with zero fill
    for (int idx = tid; idx < NPOS * 4; idx += 512) {
        int pos = idx >> 2;
        int cq  = (idx & 3) << 2;
        int r   = pos / SW;
        int cl  = pos - r * SW;
        int gh  = h0 - 7 + r;
        int gw  = w0 - 7 + cl;
        float4 kv = make_float4(0.f, 0.f, 0.f, 0.f);
        float4 vv = kv;
        if ((unsigned)gh < HH && (unsigned)gw < WW) {
            size_t off = ((size_t)(gh * WW + gw)) * CG + cq;
            kv = *(const float4*)(Kg + off);
            vv = *(const float4*)(Vg + off);
        }
        *(float4*)(Ks + pos * CG + cq) = kv;
        *(float4*)(Vs + pos * CG + cq) = vv;
    }
    __syncthreads();

    // q, pre-scaled by log2(e) so weights = exp2(logit)
    float4 qf = *(const float4*)(g_q +
        ((size_t)((b * GG + g) * HH + h) * WW + w) * CG + cof);
    float q0 = qf.x * L2E, q1 = qf.y * L2E, q2 = qf.z * L2E, q3 = qf.w * L2E;

    // Partial (this quartet's) separable rel bias (already log2e-scaled via q)
    float bias[7];
#pragma unroll
    for (int i = 0; i < 7; i++) bias[i] = 0.f;
    {
        const float* rel = (g < 4) ? (relh + (g * CG + cof) * 7)
                                   : (relw + ((g - 4) * CG + cof) * 7);
#pragma unroll
        for (int i = 0; i < 7; i++)
            bias[i] = fmaf(q0, rel[i], fmaf(q1, rel[7 + i],
                      fmaf(q2, rel[14 + i], q3 * rel[21 + i])));
    }

    int lr_ = row + 7, lc_ = col + 7;        // local (halo) center coords

    // ---- Main 7x7 window: independent per-position chains, no max ----
    float s = 0.f;
    ull o01 = pk2(0.f, 0.f), o23 = o01;
#pragma unroll
    for (int di = 0; di < 7; di++) {
        const float* kb = Ks + ((lr_ - 3 + di) * SW + (lc_ - 3)) * CG + cof;
        const float* vb = Vs + ((lr_ - 3 + di) * SW + (lc_ - 3)) * CG + cof;
#pragma unroll
        for (int dj = 0; dj < 7; dj++) {
            float4 k = *(const float4*)(kb + dj * CG);
            float bb = (g < 4) ? bias[di] : bias[dj];
            float l = fmaf(q0, k.x, fmaf(q1, k.y, fmaf(q2, k.z, fmaf(q3, k.w, bb))));
            l += __shfl_xor_sync(0xffffffffu, l, 1);
            l += __shfl_xor_sync(0xffffffffu, l, 2);
            float e = ex2(l);
            s += e;
            ull ep = pk2(e, e);
            ulonglong2 vv = *(const ulonglong2*)(vb + dj * CG);
            fma2(o01, ep, vv.x);
            fma2(o23, ep, vv.y);
        }
    }
    {
        float inv = 1.f / s;
        ull ip = pk2(inv, inv);
        mul2(o01, o01, ip);
        mul2(o23, o23, ip);
    }

    // ---- Refine: row window (same h, w-7..w+7) ----
    {
        const float* kb = Ks + (lr_ * SW + col) * CG + cof;
        const float* vb = Vs + (lr_ * SW + col) * CG + cof;
        float sr = 0.f;
        ull r01 = pk2(0.f, 0.f), r23 = r01;
#pragma unroll
        for (int j = 0; j < 15; j++) {
            float4 k = *(const float4*)(kb + j * CG);
            float l = fmaf(q0, k.x, fmaf(q1, k.y, fmaf(q2, k.z, q3 * k.w)));
            l += __shfl_xor_sync(0xffffffffu, l, 1);
            l += __shfl_xor_sync(0xffffffffu, l, 2);
            float e = ex2(l);
            sr += e;
            ull ep = pk2(e, e);
            ulonglong2 vv = *(const ulonglong2*)(vb + j * CG);
            fma2(r01, ep, vv.x);
            fma2(r23, ep, vv.y);
        }
        float ir = 1.f / sr;
        ull ip = pk2(ir, ir);
        fma2(o01, ip, r01);
        fma2(o23, ip, r23);
    }

    // ---- Refine: column window (same w, h-7..h+7) ----
    {
        const float* kb = Ks + (row * SW + lc_) * CG + cof;
        const float* vb = Vs + (row * SW + lc_) * CG + cof;
        float sc = 0.f;
        ull r01 = pk2(0.f, 0.f), r23 = r01;
#pragma unroll
        for (int j = 0; j < 15; j++) {
            float4 k = *(const float4*)(kb + j * SW * CG);
            float l = fmaf(q0, k.x, fmaf(q1, k.y, fmaf(q2, k.z, q3 * k.w)));
            l += __shfl_xor_sync(0xffffffffu, l, 1);
            l += __shfl_xor_sync(0xffffffffu, l, 2);
            float e = ex2(l);
            sc += e;
            ull ep = pk2(e, e);
            ulonglong2 vv = *(const ulonglong2*)(vb + j * SW * CG);
            fma2(r01, ep, vv.x);
            fma2(r23, ep, vv.y);
        }
        float ic = 1.f / sc;
        ull ip = pk2(ic, ic);
        fma2(o01, ip, r01);
        fma2(o23, ip, r23);
    }

    // Output: standard [b][oc][h][w]
    float o0, o1, o2, o3;
    upk2(o01, o0, o1);
    upk2(o23, o2, o3);
    size_t ob = ((size_t)(b * CC + g * CG + cof) << 12) + h * WW + w;
    out[ob]          = o0;
    out[ob + 4096]   = o1;
    out[ob + 2*4096] = o2;
    out[ob + 3*4096] = o3;
}

// ---------------------------------------------------------------------------
extern "C" void kernel_launch(void* const* d_in, const int* in_sizes, int n_in,
                              void* d_out, int out_size)
{
    const float* fm = (const float*)d_in[0];
    const float* wq = (const float*)d_in[1];
    const float* wk = (const float*)d_in[2];
    const float* wv = (const float*)d_in[3];
    const float* rh = (const float*)d_in[4];
    const float* rw = (const float*)d_in[5];
    float* out = (float*)d_out;

    cudaFuncSetAttribute(attn_kernel,
                         cudaFuncAttributeMaxDynamicSharedMemorySize, SMEM_BYTES);

    dim3 g1(128, 1, 3);                    // 8192 px / 64 per block, z = Q/K/V
    qkv_gemm<<<g1, 256>>>(fm, wq, wk, wv);

    dim3 g2(WW / TW, HH / TH, BB * GG);    // (4, 8, 16)
    attn_kernel<<<g2, 512, SMEM_BYTES>>>(rh, rw, out);
}

// round 12
// speedup vs baseline: 1.7448x; 1.1389x over previous
#include <cuda_runtime.h>

// Problem constants
#define BB 2
#define CC 128
#define GG 8
#define CG 16
#define HH 64
#define WW 64

// Attention tile: 8 rows x 16 cols, halo 7 each side
#define TH 8
#define TW 16
#define SH 22              // TH + 14
#define SW 30              // TW + 14
#define NPOS (SH*SW)       // 660 halo positions
#define SSTR 20            // padded floats per position (bank-conflict-free)
#define SMEM_FLOATS (2*NPOS*SSTR + 112)
#define SMEM_BYTES (SMEM_FLOATS*4)   // 106,048 B -> 2 blocks/SM

#define L2E 1.4426950408889634f

// Transposed scratch: [b][g][h][w][c], 16-ch contiguous (64B)
__device__ float g_q[BB*GG*HH*WW*CG];
__device__ float g_k[BB*GG*HH*WW*CG];
__device__ float g_v[BB*GG*HH*WW*CG];

typedef unsigned long long ull;
__device__ __forceinline__ ull pk2(float lo, float hi) {
    ull r; asm("mov.b64 %0, {%1, %2};" : "=l"(r) : "f"(lo), "f"(hi)); return r;
}
__device__ __forceinline__ void upk2(ull v, float& lo, float& hi) {
    asm("mov.b64 {%0, %1}, %2;" : "=f"(lo), "=f"(hi) : "l"(v));
}
__device__ __forceinline__ void fma2(ull& d, ull a, ull b) {
    asm("fma.rn.f32x2 %0, %1, %2, %0;" : "+l"(d) : "l"(a), "l"(b));
}
__device__ __forceinline__ void mul2(ull& d, ull a, ull b) {
    asm("mul.rn.f32x2 %0, %1, %2;" : "=l"(d) : "l"(a), "l"(b));
}
__device__ __forceinline__ ull add2(ull a, ull b) {
    ull r; asm("add.rn.f32x2 %0, %1, %2;" : "=l"(r) : "l"(a), "l"(b)); return r;
}
__device__ __forceinline__ float ex2(float x) {
    float r; asm("ex2.approx.f32 %0, %1;" : "=f"(r) : "f"(x)); return r;
}

// ---------------------------------------------------------------------------
// Kernel 1: Q/K/V 1x1 conv as tiled GEMM (R2 scalar version, proven ~13us).
// grid.z: 0=Q(from fm[:,128:]), 1=K, 2=V. 256 thr, 64 pixels x 128 oc.
// ---------------------------------------------------------------------------
__global__ __launch_bounds__(256) void qkv_gemm(
    const float* __restrict__ fm,
    const float* __restrict__ wq,
    const float* __restrict__ wk,
    const float* __restrict__ wv)
{
    __shared__ float wS[128][33];   // [oc][kk], padded
    __shared__ float xS[32][64];    // [kk][pixel]

    int z = blockIdx.z;
    const float* w  = (z == 0) ? wq : (z == 1 ? wk : wv);
    int coff        = (z == 0) ? 128 : 0;

    int t    = threadIdx.x;
    int pix0 = blockIdx.x * 64;
    int b    = pix0 >> 12;
    int rem0 = pix0 & 4095;

    const float* xbase = fm + ((size_t)(b * 256 + coff) << 12) + rem0;

    int ocb = (t >> 4) << 3;               // 0..120 step 8
    int pxb = (t & 15) << 2;               // 0..60 step 4

    float acc[8][4];
#pragma unroll
    for (int u = 0; u < 8; u++)
#pragma unroll
        for (int p = 0; p < 4; p++) acc[u][p] = 0.f;

    for (int ic0 = 0; ic0 < 128; ic0 += 32) {
#pragma unroll
        for (int j = 0; j < 16; j++) {
            int idx = t + j * 256;
            wS[idx >> 5][idx & 31] = w[(idx >> 5) * 128 + ic0 + (idx & 31)];
        }
#pragma unroll
        for (int j = 0; j < 8; j++) {
            int idx = t + j * 256;
            xS[idx >> 6][idx & 63] =
                xbase[(size_t)(ic0 + (idx >> 6)) * 4096 + (idx & 63)];
        }
        __syncthreads();

#pragma unroll
        for (int kk = 0; kk < 32; kk++) {
            float x0 = xS[kk][pxb + 0];
            float x1 = xS[kk][pxb + 1];
            float x2 = xS[kk][pxb + 2];
            float x3 = xS[kk][pxb + 3];
#pragma unroll
            for (int u = 0; u < 8; u++) {
                float wv_ = wS[ocb + u][kk];
                acc[u][0] += wv_ * x0;
                acc[u][1] += wv_ * x1;
                acc[u][2] += wv_ * x2;
                acc[u][3] += wv_ * x3;
            }
        }
        __syncthreads();
    }

    float* dst = (z == 0) ? g_q : (z == 1 ? g_k : g_v);
    int g  = ocb >> 4;
    int c0 = ocb & 15;         // 0 or 8
#pragma unroll
    for (int p = 0; p < 4; p++) {
        int pix = rem0 + pxb + p;
        int h = pix >> 6;
        int ww_ = pix & 63;
        size_t base = ((size_t)((b * GG + g) * HH + h) * WW + ww_) * CG + c0;
        *(float4*)(dst + base)     = make_float4(acc[0][p], acc[1][p], acc[2][p], acc[3][p]);
        *(float4*)(dst + base + 4) = make_float4(acc[4][p], acc[5][p], acc[6][p], acc[7][p]);
    }
}

// ---------------------------------------------------------------------------
// Kernel 2: fused windowed attention. One THREAD per pixel (full 16-ch dot,
// packed f32x2), zero shuffles. Block = 8x16 tile = 128 threads. Smem
// position stride = 20 floats -> conflict-free LDS.128 in every 8-lane phase.
// No-max softmax + ex2 with log2e folded into q.
// ---------------------------------------------------------------------------
__global__ __launch_bounds__(128, 2) void attn_kernel(
    const float* __restrict__ relh,
    const float* __restrict__ relw,
    float* __restrict__ out)
{
    extern __shared__ float sh[];
    float* Ks   = sh;                        // NPOS * SSTR
    float* Vs   = sh + NPOS * SSTR;
    float* relS = sh + 2 * NPOS * SSTR;      // 112 floats (this block's group)

    int tid = threadIdx.x;
    int row = tid >> 4;          // 0..7
    int col = tid & 15;          // 0..15

    int bz = blockIdx.z;
    int b  = bz >> 3;
    int g  = bz & 7;
    int h0 = blockIdx.y * TH;
    int w0 = blockIdx.x * TW;
    int h  = h0 + row, w = w0 + col;

    const float* Kg = g_k + (size_t)(b * GG + g) * (HH * WW * CG);
    const float* Vg = g_v + (size_t)(b * GG + g) * (HH * WW * CG);

    // Halo load with zero fill (coalesced LDG; padded stride-20 STS)
    for (int idx = tid; idx < NPOS * 4; idx += 128) {
        int pos = idx >> 2;
        int cq  = (idx & 3) << 2;
        int r   = pos / SW;
        int cl  = pos - r * SW;
        int gh  = h0 - 7 + r;
        int gw  = w0 - 7 + cl;
        float4 kv = make_float4(0.f, 0.f, 0.f, 0.f);
        float4 vv = kv;
        if ((unsigned)gh < HH && (unsigned)gw < WW) {
            size_t off = ((size_t)(gh * WW + gw)) * CG + cq;
            kv = *(const float4*)(Kg + off);
            vv = *(const float4*)(Vg + off);
        }
        *(float4*)(Ks + pos * SSTR + cq) = kv;
        *(float4*)(Vs + pos * SSTR + cq) = vv;
    }
    // This block's rel slice (16 ch x 7)
    if (tid < 112)
        relS[tid] = (g < 4) ? relh[g * 112 + tid] : relw[(g - 4) * 112 + tid];
    __syncthreads();

    // q (16 ch), pre-scaled by log2(e)
    const float* qp = g_q + ((size_t)((b * GG + g) * HH + h) * WW + w) * CG;
    float qs[16];
#pragma unroll
    for (int i = 0; i < 4; i++) {
        float4 qf = *(const float4*)(qp + i * 4);
        qs[i*4+0] = qf.x * L2E; qs[i*4+1] = qf.y * L2E;
        qs[i*4+2] = qf.z * L2E; qs[i*4+3] = qf.w * L2E;
    }

    // Separable rel bias (log2-scaled via q); broadcast LDS
    float bias[7];
#pragma unroll
    for (int i = 0; i < 7; i++) {
        float bsum = 0.f;
#pragma unroll
        for (int c = 0; c < 16; c++)
            bsum = fmaf(qs[c], relS[c * 7 + i], bsum);
        bias[i] = bsum;
    }

    ull q2[8];
#pragma unroll
    for (int i = 0; i < 8; i++) q2[i] = pk2(qs[2*i], qs[2*i+1]);

    bool gh4 = (g < 4);

    // ---- Main 7x7 window ----
    float s = 0.f;
    ull o[8];
#pragma unroll
    for (int i = 0; i < 8; i++) o[i] = pk2(0.f, 0.f);

#pragma unroll
    for (int di = 0; di < 7; di++) {
        int pbase = (row + 4 + di) * SW + (col + 4);
#pragma unroll
        for (int dj = 0; dj < 7; dj++) {
            const float* kp = Ks + (pbase + dj) * SSTR;
            ulonglong2 ka = *(const ulonglong2*)(kp);
            ulonglong2 kb = *(const ulonglong2*)(kp + 4);
            ulonglong2 kc = *(const ulonglong2*)(kp + 8);
            ulonglong2 kd = *(const ulonglong2*)(kp + 12);
            float bb = gh4 ? bias[di] : bias[dj];
            ull a0 = pk2(bb, 0.f), a1 = pk2(0.f, 0.f);
            fma2(a0, q2[0], ka.x); fma2(a1, q2[1], ka.y);
            fma2(a0, q2[2], kb.x); fma2(a1, q2[3], kb.y);
            fma2(a0, q2[4], kc.x); fma2(a1, q2[5], kc.y);
            fma2(a0, q2[6], kd.x); fma2(a1, q2[7], kd.y);
            float lo, hi; upk2(add2(a0, a1), lo, hi);
            float e = ex2(lo + hi);
            s += e;
            ull ep = pk2(e, e);
            const float* vp = Vs + (pbase + dj) * SSTR;
            ulonglong2 va = *(const ulonglong2*)(vp);
            ulonglong2 vb = *(const ulonglong2*)(vp + 4);
            ulonglong2 vc = *(const ulonglong2*)(vp + 8);
            ulonglong2 vd = *(const ulonglong2*)(vp + 12);
            fma2(o[0], ep, va.x); fma2(o[1], ep, va.y);
            fma2(o[2], ep, vb.x); fma2(o[3], ep, vb.y);
            fma2(o[4], ep, vc.x); fma2(o[5], ep, vc.y);
            fma2(o[6], ep, vd.x); fma2(o[7], ep, vd.y);
        }
    }
    {
        float inv = 1.f / s;
        ull ip = pk2(inv, inv);
#pragma unroll
        for (int i = 0; i < 8; i++) mul2(o[i], o[i], ip);
    }

    // ---- Refine windows: row (h fixed) then col (w fixed), no bias ----
#pragma unroll
    for (int pass = 0; pass < 2; pass++) {
        float sr = 0.f;
        ull r[8];
#pragma unroll
        for (int i = 0; i < 8; i++) r[i] = pk2(0.f, 0.f);
#pragma unroll
        for (int j = 0; j < 15; j++) {
            int pos = (pass == 0) ? ((row + 7) * SW + col + j)
                                  : ((row + j) * SW + col + 7);
            const float* kp = Ks + pos * SSTR;
            ulonglong2 ka = *(const ulonglong2*)(kp);
            ulonglong2 kb = *(const ulonglong2*)(kp + 4);
            ulonglong2 kc = *(const ulonglong2*)(kp + 8);
            ulonglong2 kd = *(const ulonglong2*)(kp + 12);
            ull a0 = pk2(0.f, 0.f), a1 = a0;
            fma2(a0, q2[0], ka.x); fma2(a1, q2[1], ka.y);
            fma2(a0, q2[2], kb.x); fma2(a1, q2[3], kb.y);
            fma2(a0, q2[4], kc.x); fma2(a1, q2[5], kc.y);
            fma2(a0, q2[6], kd.x); fma2(a1, q2[7], kd.y);
            float lo, hi; upk2(add2(a0, a1), lo, hi);
            float e = ex2(lo + hi);
            sr += e;
            ull ep = pk2(e, e);
            const float* vp = Vs + pos * SSTR;
            ulonglong2 va = *(const ulonglong2*)(vp);
            ulonglong2 vb = *(const ulonglong2*)(vp + 4);
            ulonglong2 vc = *(const ulonglong2*)(vp + 8);
            ulonglong2 vd = *(const ulonglong2*)(vp + 12);
            fma2(r[0], ep, va.x); fma2(r[1], ep, va.y);
            fma2(r[2], ep, vb.x); fma2(r[3], ep, vb.y);
            fma2(r[4], ep, vc.x); fma2(r[5], ep, vc.y);
            fma2(r[6], ep, vd.x); fma2(r[7], ep, vd.y);
        }
        float ir = 1.f / sr;
        ull ip = pk2(ir, ir);
#pragma unroll
        for (int i = 0; i < 8; i++) fma2(o[i], ip, r[i]);
    }

    // Output: standard [b][oc][h][w]
    size_t ob = ((size_t)(b * CC + g * CG) << 12) + h * WW + w;
#pragma unroll
    for (int i = 0; i < 8; i++) {
        float lo, hi; upk2(o[i], lo, hi);
        out[ob + (size_t)(2*i)     * 4096] = lo;
        out[ob + (size_t)(2*i + 1) * 4096] = hi;
    }
}

// ---------------------------------------------------------------------------
extern "C" void kernel_launch(void* const* d_in, const int* in_sizes, int n_in,
                              void* d_out, int out_size)
{
    const float* fm = (const float*)d_in[0];
    const float* wq = (const float*)d_in[1];
    const float* wk = (const float*)d_in[2];
    const float* wv = (const float*)d_in[3];
    const float* rh = (const float*)d_in[4];
    const float* rw = (const float*)d_in[5];
    float* out = (float*)d_out;

    cudaFuncSetAttribute(attn_kernel,
                         cudaFuncAttributeMaxDynamicSharedMemorySize, SMEM_BYTES);

    dim3 g1(128, 1, 3);                    // 8192 px / 64 per block, z = Q/K/V
    qkv_gemm<<<g1, 256>>>(fm, wq, wk, wv);

    dim3 g2(WW / TW, HH / TH, BB * GG);    // (4, 8, 16)
    attn_kernel<<<g2, 128, SMEM_BYTES>>>(rh, rw, out);
}